// round 17
// baseline (speedup 1.0000x reference)
#include <cuda_runtime.h>
#include <math.h>

#define N_PIX_MAX 4194304
#define N_BINS    350000
#define ACC4      (N_BINS / 2)              // float4 pairs in g_acc
#define TAPS      901
#define HALF      450
#define CHALF     900                       // composite kernel half-width
#define COMP_N    2112                      // composite kernel storage (>=1801)
#define CONV_THREADS 128
#define RPT       8                         // float2 output-pairs per thread
#define RING      8                         // u64 ring slots (elements mod 8)
#define HTILE     (CONV_THREADS * RPT)      // 1024 (per half)
#define TILE_OUT  (2 * HTILE)               // 2048 outputs per block
#define RAW2      (HTILE + 2*CHALF + 16)    // 2840 float2 window (+refill slack)
#define PAD2      (RAW2 + (RAW2 >> 3))      // bank-conflict padding (1 per 8)
#define WSH2_N    512                       // composite support slots (<=504 taps)
#define P2(i)     ((i) + ((i) >> 3))
#define JMAX      80                        // max one-sided mid-overhang (~66)
#define NC        64                        // corrected outputs per side
#define PREP_ZB   171                       // zero blocks in prep kernel

typedef unsigned long long u64;

// ---------------- device scratch (no allocations allowed) ----------------
__device__ float g_rot[TAPS];
__device__ float g_gauss[TAPS];
__device__ float g_comp[COMP_N];            // composite kernel K = k1 (*) k2
__device__ int   g_lo8;                     // composite support lo, 8-aligned
__device__ int   g_nblk;                    // # of 8-tap blocks
__device__ int   g_b[4];                    // lo0, hi0, lo1, hi1
__device__ float g_corr_lo[NC];             // boundary corrections, low side
__device__ float g_corr_hi[NC];             // boundary corrections, high side
__device__ __align__(16) float g_acc[2 * N_BINS];   // interleaved (sum, cnt)

// ------- prep: zero accumulators (blocks 0..170) + build k1,k2, bounds,
//         boundary corrections (block 171). Independent work, one launch. --
__global__ void prep_kernel(const float* __restrict__ ln_sigma,
                            const float* __restrict__ ln_vsini,
                            const float* __restrict__ f, int n) {
    int tid = threadIdx.x;

    if (blockIdx.x != PREP_ZB) {            // -------- zero slice ----------
        int i = blockIdx.x * 1024 + tid;
        if (i < ACC4)
            ((float4*)g_acc)[i] = make_float4(0.f, 0.f, 0.f, 0.f);
        return;
    }

    // ------------------------- setup block ------------------------------
    __shared__ float red[1024];
    __shared__ float sk1[904], sk2[904];
    __shared__ float sfl[JMAX], sfh[JMAX];      // f near low/high boundary
    __shared__ float smidl[JMAX], smidh[JMAX];  // mid[-1-t], mid[n+t]
    __shared__ int s_lo0, s_hi0, s_lo1, s_hi1;
    if (tid == 0) { s_lo0 = TAPS; s_hi0 = -1; s_lo1 = TAPS; s_hi1 = -1; }
    __syncthreads();

    float vsini = 0.9f + expf(ln_vsini[0]);
    float sigma = 0.01f + expf(ln_sigma[0]);

    float w  = 0.0f;   // rotational tap (pre-normalization)
    float gw = 0.0f;   // gaussian tap
    if (tid < TAPS) {
        float g = -4.5f + 0.01f * (float)tid;   // linspace(-4.5,4.5,901)
        float x  = (299792.458f * g / 10500.0f) / vsini;
        float x2 = fminf(x * x, 1.0f);
        if (x2 < 0.99999999f) {
            w = 2.0f * sqrtf(1.0f - x2);
            atomicMin(&s_lo0, tid);
            atomicMax(&s_hi0, tid);
        }
        float e = expf(-0.5f * g * g / (sigma * sigma));
        // ~4.5-sigma cutoff: truncated tail mass ~3.4e-6 relative (<< 1e-3 tol)
        if (e >= 4e-5f) {
            atomicMin(&s_lo1, tid);
            atomicMax(&s_hi1, tid);
        }
        gw = (0.01f / (sigma * sqrtf(2.0f * 3.1415926654f))) * e;
    }

    // block sum of rotational kernel for normalization
    red[tid] = w;
    __syncthreads();
    for (int s = 512; s > 0; s >>= 1) {
        if (tid < s) red[tid] += red[tid + s];
        __syncthreads();
    }
    float total = red[0];

    if (tid < TAPS) {
        float k1 = w / total;
        sk1[tid] = k1;  g_rot[tid]   = k1;
        sk2[tid] = gw;  g_gauss[tid] = gw;
    } else if (tid < 904) {
        sk1[tid] = 0.0f;
        sk2[tid] = 0.0f;
    }
    __syncthreads();

    int lo0 = s_lo0, hi0 = s_hi0, lo1 = s_lo1, hi1 = s_hi1;
    if (tid == 0) {
        int lo = lo0 + lo1;
        int hi = hi0 + hi1;
        int lo8 = lo & ~7;
        int nblk = ((hi - lo8 + 1) + 7) >> 3;
        if (nblk > (WSH2_N - 8) / 8) nblk = (WSH2_N - 8) / 8;  // safety clamp
        g_lo8  = lo8;
        g_nblk = nblk;
        g_b[0] = lo0; g_b[1] = hi0; g_b[2] = lo1; g_b[3] = hi1;
    }

    // ---- boundary corrections ----
    int JL = hi0 - HALF;  if (JL < 0) JL = 0;  if (JL > JMAX) JL = JMAX;
    int JH = HALF - lo0;  if (JH < 0) JH = 0;  if (JH > JMAX) JH = JMAX;

    for (int j = tid; j < JL; j += 1024) sfl[j] = f[j];
    for (int j = tid; j < JH; j += 1024) sfh[j] = f[n - 1 - j];  // sfh[m]=f[n-1-m]
    __syncthreads();

    // mid values outside [0,n):
    if (tid < JL) {
        int jn = tid + 1;
        float s = 0.0f;
        int mmax = hi0 - HALF - jn;
        for (int m = 0; m <= mmax; ++m)
            s += sk1[m + HALF + jn] * sfl[m];
        smidl[tid] = s;
    } else if (tid >= 128 && tid - 128 < JH) {
        int jn = tid - 127;
        float s = 0.0f;
        int mmax = HALF - jn - lo0;
        for (int m = 0; m <= mmax; ++m)
            s += sk1[HALF - jn - m] * sfh[m];
        smidh[jn - 1] = s;
    }
    __syncthreads();

    // corrections:
    if (tid >= 256 && tid < 256 + NC) {
        int i = tid - 256;
        float s = 0.0f;
        for (int jn = 1; jn <= JL; ++jn) {
            int idx = HALF - i - jn;
            if (idx >= 0) s += sk2[idx] * smidl[jn - 1];
        }
        g_corr_lo[i] = s;
    } else if (tid >= 384 && tid < 384 + NC) {
        int ii = tid - 384;                    // output i = n - NC + ii
        float s = 0.0f;
        for (int jn = 1; jn <= JH; ++jn) {
            int idx = (NC - 1 - ii) + HALF + jn;
            if (idx <= 900) s += sk2[idx] * smidh[jn - 1];
        }
        g_corr_hi[ii] = s;
    }
}

// ------- composite K[c] = sum_a k1[a]*k2[c-a], parallel across 9 blocks ---
__global__ void comp_kernel() {
    __shared__ float sk1[904], sk2[904];
    int tid = threadIdx.x;
    for (int j = tid; j < 904; j += 256) {
        sk1[j] = (j < TAPS) ? g_rot[j]   : 0.0f;
        sk2[j] = (j < TAPS) ? g_gauss[j] : 0.0f;
    }
    __syncthreads();
    int c = blockIdx.x * 256 + tid;
    if (c < COMP_N) {
        int lo0 = g_b[0], hi0 = g_b[1], lo1 = g_b[2], hi1 = g_b[3];
        float s = 0.0f;
        int a0 = max(lo0, c - hi1);
        int a1 = min(hi0, c - lo1);
        for (int a = a0; a <= a1; ++a)
            s += sk1[a] * sk2[c - a];
        g_comp[c] = s;
    }
}

// ---- run-length accumulate 8 register values into interleaved (s,c) bins --
__device__ __forceinline__ void seg_accum8(const int* __restrict__ ids,
                                           const float* v, int o, int n) {
    if (o >= n) return;
    if (o + RPT <= n) {
        int4 ia = *(const int4*)(ids + o);
        int4 ib = *(const int4*)(ids + o + 4);
        int id[8] = {ia.x, ia.y, ia.z, ia.w, ib.x, ib.y, ib.z, ib.w};
        int cur = id[0];
        float s = 0.0f, c = 0.0f;
#pragma unroll
        for (int r = 0; r < RPT; ++r) {
            if (id[r] != cur) {
                atomicAdd(&g_acc[2 * cur],     s);
                atomicAdd(&g_acc[2 * cur + 1], c);
                cur = id[r]; s = 0.0f; c = 0.0f;
            }
            s += v[r];
            c += 1.0f;
        }
        atomicAdd(&g_acc[2 * cur],     s);
        atomicAdd(&g_acc[2 * cur + 1], c);
    } else {
        for (int r = 0; r < RPT && o + r < n; ++r) {
            int id = ids[o + r];
            atomicAdd(&g_acc[2 * id],     v[r]);
            atomicAdd(&g_acc[2 * id + 1], 1.0f);
        }
    }
}

// -------- fused conv + segment accumulation (no conv-array round-trip) ----
// Weight taps consumed in PAIRS via one 16B LDS (wsh2[woff+u] is 16B-aligned
// for even u since woff ≡ 0 mod 8) -> weight-LDS count halves.
__global__ void __launch_bounds__(CONV_THREADS, 7)
conv_kernel(const float* __restrict__ in, const int* __restrict__ ids, int n) {
    __shared__ float2 sh2[PAD2];
    __shared__ __align__(16) float2 wsh2[WSH2_N];

    const int lo8  = g_lo8;            // multiple of 8
    const int nblk = g_nblk;           // number of 8-tap blocks

    const int tile0 = blockIdx.x * TILE_OUT;
    const int tid   = threadIdx.x;

    for (int j = tid; j < WSH2_N; j += CONV_THREADS) {
        int c = lo8 + j;
        float wv = (c < COMP_N) ? g_comp[c] : 0.0f;
        wsh2[j] = make_float2(wv, wv);
    }
    for (int j = tid; j < RAW2; j += CONV_THREADS) {
        int g1 = tile0 - CHALF + j;
        int g2 = g1 + HTILE;
        float a = (g1 >= 0 && g1 < n) ? in[g1] : 0.0f;
        float b = (g2 >= 0 && g2 < n) ? in[g2] : 0.0f;
        sh2[P2(j)] = make_float2(a, b);
    }
    __syncthreads();

    const int base = tid * RPT;        // float2-index of first output pair
    u64 x[RING], acc[RPT];
    int roff = P2(base + lo8);         // padded index of ring start
#pragma unroll
    for (int s = 0; s < RING; ++s) {
        x[s]   = *(const u64*)&sh2[roff + s];     // P2(k0+s)=P2(k0)+s, s<8
        acc[s] = 0ull;                 // (0.0f, 0.0f)
    }
    roff += 9;                         // refill base: P2(k0+8) = P2(k0)+9

    int woff = 0;                      // weight index within wsh2
    ulonglong2 wp2 = *(const ulonglong2*)&wsh2[0];   // packed taps {0,1}
    for (int b = 0; b < nblk; ++b) {
#pragma unroll
        for (int u = 0; u < 8; u += 2) {   // taps lo8+8b+u, +u+1
            ulonglong2 wp2n = *(const ulonglong2*)&wsh2[woff + u + 2];
            // ---- tap u (weight wp2.x) ----
            asm("fma.rn.f32x2 %0, %1, %2, %0;"
                : "+l"(acc[0]) : "l"(x[u]), "l"(wp2.x));
            u64 xf0 = *(const u64*)&sh2[roff + u];       // element tap+8
#pragma unroll
            for (int r = 1; r < RPT; ++r)
                asm("fma.rn.f32x2 %0, %1, %2, %0;"
                    : "+l"(acc[r]) : "l"(x[(u + r) & 7]), "l"(wp2.x));
            x[u] = xf0;
            // ---- tap u+1 (weight wp2.y) ----
            asm("fma.rn.f32x2 %0, %1, %2, %0;"
                : "+l"(acc[0]) : "l"(x[u + 1]), "l"(wp2.y));
            u64 xf1 = *(const u64*)&sh2[roff + u + 1];   // element tap+9
#pragma unroll
            for (int r = 1; r < RPT; ++r)
                asm("fma.rn.f32x2 %0, %1, %2, %0;"
                    : "+l"(acc[r]) : "l"(x[(u + 1 + r) & 7]), "l"(wp2.y));
            x[u + 1] = xf1;
            wp2 = wp2n;
        }
        roff += 9;                     // next block's refill base
        woff += 8;
    }

    // unpack: low 32 bits = first-half output, high = second-half
    float lo_v[RPT], hi_v[RPT];
#pragma unroll
    for (int r = 0; r < RPT; ++r) {
        lo_v[r] = __int_as_float((int)(acc[r] & 0xFFFFFFFFull));
        hi_v[r] = __int_as_float((int)(acc[r] >> 32));
    }

    int o1 = tile0 + base;
    int o2 = o1 + HTILE;

    // boundary corrections (only 8 threads chip-wide take these)
    if (blockIdx.x == 0 && tid < (NC / RPT)) {
#pragma unroll
        for (int r = 0; r < RPT; ++r)
            lo_v[r] -= g_corr_lo[base + r];          // outputs 0..NC-1
    }
    if (blockIdx.x == gridDim.x - 1) {
#pragma unroll
        for (int r = 0; r < RPT; ++r) {
            int idx = o2 + r - (n - NC);
            if (idx >= 0 && idx < NC) hi_v[r] -= g_corr_hi[idx];
        }
    }

    // segment accumulation straight from registers (ids are sorted)
    seg_accum8(ids, lo_v, o1, n);
    seg_accum8(ids, hi_v, o2, n);
}

// ---------------- means, clip, drop first/last bin -----------------------
// One float4 = two complete (sum, cnt) bins.
__global__ void final_kernel(float* __restrict__ out, int n_out) {
    int t = blockIdx.x * blockDim.x + threadIdx.x;
    if (t >= ACC4) return;
    float4 v = ((const float4*)g_acc)[t];    // bins 2t (v.x,v.y), 2t+1 (v.z,v.w)
    int b = 2 * t;
    if (b >= 1 && b <= n_out) {
        float m = v.x / fmaxf(v.y, 1.0f);
        out[b - 1] = fminf(fmaxf(m, 0.0f), 1.0f);
    }
    b = 2 * t + 1;
    if (b >= 1 && b <= n_out) {
        float m = v.z / fmaxf(v.w, 1.0f);
        out[b - 1] = fminf(fmaxf(m, 0.0f), 1.0f);
    }
}

extern "C" void kernel_launch(void* const* d_in, const int* in_sizes, int n_in,
                              void* d_out, int out_size) {
    const float* flux     = (const float*)d_in[0];
    const float* ln_sigma = (const float*)d_in[1];
    const float* ln_vsini = (const float*)d_in[2];
    const int*   ids      = (const int*)d_in[3];
    int n = in_sizes[0];

    prep_kernel<<<PREP_ZB + 1, 1024>>>(ln_sigma, ln_vsini, flux, n);
    comp_kernel<<<(COMP_N + 255) / 256, 256>>>();

    int conv_blocks = (n + TILE_OUT - 1) / TILE_OUT;
    conv_kernel<<<conv_blocks, CONV_THREADS>>>(flux, ids, n);

    final_kernel<<<(ACC4 + 255) / 256, 256>>>((float*)d_out, out_size);
}